// round 15
// baseline (speedup 1.0000x reference)
#include <cuda_runtime.h>
#include <cuda_bf16.h>

// PatchMatch (b=1, c=192, h=w=128); fixed: iteration_count=2, minWH=127, is_final=1.
// Launch plan (15 kernels, PDL overlap on all eval->eval edges):
//   transpose | prop_first(k=1,init) prop(2..32)x5 rand7A(prop64+7 rand)
//             | prop(1..32)x6 rand7B(prop64+7 rand+output)
// Prop kernels run SINGLE-WAVE: 1024 blocks x 128 thr, 4 pixels per warp
// (p = warp + i*4096), removing wave-transition overhead per launch.

#define C 192
#define NF4 48          // 192 floats = 48 float4
#define H 128
#define W 128
#define NPIX (H * W)
#define NWARP 4096      // single-wave warp count; 4 pixels per warp

#define PDL_SIGNAL() asm volatile("griddepcontrol.launch_dependents;")
#define PDL_WAIT()   asm volatile("griddepcontrol.wait;" ::: "memory")

__device__ float4 g_in_t4[NPIX * NF4];    // pixel-major input  [p][48]
__device__ float4 g_ref_t4[NPIX * NF4];   // pixel-major ref    [p][48]
__device__ int2   g_state[2][NPIX];       // {packed y*128+x, float bits of score}

__constant__ int c_DX[9] = {0, -1, -1, 0, 0, 0, 1, 1, 0};
__constant__ int c_DY[9] = {1, 0, 0, 1, 0, -1, 0, 0, -1};

// ---------------------------------------------------------------------------
// Vectorized transpose [C][NPIX] -> [NPIX][C]. Tile: 32 channels x 128 pixels.
__global__ __launch_bounds__(256) void transpose_kernel(
    const float* __restrict__ in0, const float* __restrict__ in1) {
    __shared__ float tile[32][129];
    const float* in = blockIdx.z ? in1 : in0;
    float* out = blockIdx.z ? (float*)g_ref_t4 : (float*)g_in_t4;
    int p0 = blockIdx.x * 128;
    int c0 = blockIdx.y * 32;
    int tid = threadIdx.x;

#pragma unroll
    for (int pass = 0; pass < 4; pass++) {
        int r = pass * 8 + (tid >> 5);
        int p4 = tid & 31;
        const float4* inv = (const float4*)(in + (size_t)(c0 + r) * NPIX + p0);
        float4 v = inv[p4];
        tile[r][4 * p4 + 0] = v.x;
        tile[r][4 * p4 + 1] = v.y;
        tile[r][4 * p4 + 2] = v.z;
        tile[r][4 * p4 + 3] = v.w;
    }
    __syncthreads();

#pragma unroll
    for (int pass = 0; pass < 4; pass++) {
        int pix = pass * 32 + (tid >> 3);
        int c4 = tid & 7;
        float4 w;
        w.x = tile[4 * c4 + 0][pix];
        w.y = tile[4 * c4 + 1][pix];
        w.z = tile[4 * c4 + 2][pix];
        w.w = tile[4 * c4 + 3][pix];
        float4* outv = (float4*)(out + (size_t)(p0 + pix) * C + c0);
        outv[c4] = w;
    }
}

// ---------------------------------------------------------------------------
// Canonical per-lane (l in [0,16)) partial dot; identical everywhere so equal
// coords give bit-identical scores. r4 is pre-offset by l.
__device__ __forceinline__ float dot48h(float4 a0, float4 a1, float4 a2,
                                        const float4* __restrict__ r4) {
    float4 r0 = r4[0], r1 = r4[16], r2 = r4[32];
    float s;
    s = a0.x * r0.x;          s = fmaf(a0.y, r0.y, s);
    s = fmaf(a0.z, r0.z, s);  s = fmaf(a0.w, r0.w, s);
    s = fmaf(a1.x, r1.x, s);  s = fmaf(a1.y, r1.y, s);
    s = fmaf(a1.z, r1.z, s);  s = fmaf(a1.w, r1.w, s);
    s = fmaf(a2.x, r2.x, s);  s = fmaf(a2.y, r2.y, s);
    s = fmaf(a2.z, r2.z, s);  s = fmaf(a2.w, r2.w, s);
    return s;
}

__device__ __forceinline__ float halfsum(float s) {
    s += __shfl_xor_sync(0xffffffffu, s, 8);
    s += __shfl_xor_sync(0xffffffffu, s, 4);
    s += __shfl_xor_sync(0xffffffffu, s, 2);
    s += __shfl_xor_sync(0xffffffffu, s, 1);
    return s;
}

__device__ __forceinline__ int reflect128(int t) {
    if (t < 0) t = -t;
    if (t > 127) t = 254 - t;
    return t;
}

// Score a pair of candidates (this half's cc; other half's via shuffle) and
// fold in index order jA then jA+1 (strict > == first-occurrence argmax).
__device__ __forceinline__ void score_pair(float4 a0, float4 a1, float4 a2, int l,
                                           int h, int cc, float& best, int& bestc) {
    float s = halfsum(dot48h(a0, a1, a2, g_ref_t4 + (size_t)cc * NF4 + l));
    float sO = __shfl_xor_sync(0xffffffffu, s, 16);
    int   cO = __shfl_xor_sync(0xffffffffu, cc, 16);
    float s0 = h ? sO : s;  int c0 = h ? cO : cc;
    float s1 = h ? s : sO;  int c1 = h ? cc : cO;
    if (s0 > best) { best = s0; bestc = c0; }
    if (s1 > best) { best = s1; bestc = c1; }
}

// One step with PRE-FETCHED candidate coords cands[4] (j = {0,2,5,7}+h).
__device__ __forceinline__ void prop_core(float4 a0, float4 a1, float4 a2,
                                          int l, int h, const int* cands,
                                          int& myc, float& sc) {
    float best = -3.4e38f; int bestc = 0;
    score_pair(a0, a1, a2, l, h, cands[0], best, bestc);
    score_pair(a0, a1, a2, l, h, cands[1], best, bestc);
    if (sc > best) { best = sc; bestc = myc; }
    score_pair(a0, a1, a2, l, h, cands[2], best, bestc);
    score_pair(a0, a1, a2, l, h, cands[3], best, bestc);
    myc = bestc; sc = best;
}

// Gather the 4 per-half candidate coords for a prop step (independent loads).
__device__ __forceinline__ void gather_cands(const int2* __restrict__ sb,
                                             int p, int k, int h, int* cands) {
    const int jb[4] = {0, 2, 5, 7};
    int y = p >> 7, x = p & 127;
#pragma unroll
    for (int i = 0; i < 4; i++) {
        int j = jb[i] + h;
        int ny = reflect128(y + k * (j / 3 - 1));
        int nx = reflect128(x + k * (j % 3 - 1));
        cands[i] = ((const int*)sb)[2 * ((ny << 7) + nx)];   // coord word only
    }
}

// ---------------------------------------------------------------------------
// Step 0 (prop, k=1) with init fused: neighbor coords straight from inref_x/y;
// center score computed as a 9th dot. Single-wave: 4 pixels per warp.
__global__ __launch_bounds__(128, 10) void prop_first_kernel(
    const float* __restrict__ inref_x, const float* __restrict__ inref_y) {
    PDL_SIGNAL();
    PDL_WAIT();
    int warp = blockIdx.x * 4 + (threadIdx.x >> 5);
    int lane = threadIdx.x & 31;
    int h = lane >> 4, l = lane & 15;

#pragma unroll
    for (int i = 0; i < 4; i++) {
        int p = warp + i * NWARP;
        int y = p >> 7, x = p & 127;

        const float4* __restrict__ a4 = g_in_t4 + (size_t)p * NF4 + l;
        float4 a0 = a4[0], a1 = a4[16], a2 = a4[32];

        const int jb[4] = {0, 2, 5, 7};
        int cands[4];
#pragma unroll
        for (int q = 0; q < 4; q++) {
            int j = jb[q] + h;
            int ny = reflect128(y + (j / 3 - 1));
            int nx = reflect128(x + (j % 3 - 1));
            int np = (ny << 7) + nx;
            cands[q] = ((int)inref_y[np] << 7) + (int)inref_x[np];
        }
        int cc4 = ((int)inref_y[p] << 7) + (int)inref_x[p];

        float best = -3.4e38f; int bestc = 0;
        score_pair(a0, a1, a2, l, h, cands[0], best, bestc);
        score_pair(a0, a1, a2, l, h, cands[1], best, bestc);
        {   // center candidate j=4
            float s4 = halfsum(dot48h(a0, a1, a2, g_ref_t4 + (size_t)cc4 * NF4 + l));
            if (s4 > best) { best = s4; bestc = cc4; }
        }
        score_pair(a0, a1, a2, l, h, cands[2], best, bestc);
        score_pair(a0, a1, a2, l, h, cands[3], best, bestc);

        if (lane == 0) g_state[0][p] = make_int2(bestc, __float_as_int(best));
    }
}

// ---------------------------------------------------------------------------
// Propagation step (k >= 2). Single-wave: 1024 blocks x 4 warps, 4 pixels per
// warp. Pixel 0's input vector prefetched before the PDL wait.
__global__ __launch_bounds__(128, 10) void prop_kernel(int k, int cur, int nxt) {
    PDL_SIGNAL();
    int warp = blockIdx.x * 4 + (threadIdx.x >> 5);
    int lane = threadIdx.x & 31;
    int h = lane >> 4, l = lane & 15;

    // prefetch pixel 0's input vector during predecessor tail
    const float4* __restrict__ a4 = g_in_t4 + (size_t)warp * NF4 + l;
    float4 a0 = a4[0], a1 = a4[16], a2 = a4[32];

    PDL_WAIT();
    const int2* __restrict__ sb = g_state[cur];

#pragma unroll
    for (int i = 0; i < 4; i++) {
        int p = warp + i * NWARP;
        if (i > 0) {
            const float4* __restrict__ b4 = g_in_t4 + (size_t)p * NF4 + l;
            a0 = b4[0]; a1 = b4[16]; a2 = b4[32];
        }
        int cands[4];
        gather_cands(sb, p, k, h, cands);
        int2 st = sb[p];
        int myc = st.x;
        float sc = __int_as_float(st.y);

        prop_core(a0, a1, a2, l, h, cands, myc, sc);

        if (lane == 0) g_state[nxt][p] = make_int2(myc, __float_as_int(sc));
    }
}

// ---------------------------------------------------------------------------
// Fused: one prop step (k=64) + 7 random-search steps (k=1..64), state in
// registers. Unchanged from R13/R14 (proven at the traffic floor).
template <int FINAL>
__global__ __launch_bounds__(256) void rand7_kernel(int prop_iter, int cur,
                                                    float* __restrict__ out,
                                                    int out_size) {
    PDL_SIGNAL();
    int warp = blockIdx.x * 8 + (threadIdx.x >> 5);
    int lane = threadIdx.x & 31;
    int h = lane >> 4, l = lane & 15;
    int p = warp;

    const float4* __restrict__ a4 = g_in_t4 + (size_t)p * NF4 + l;
    float4 a0 = a4[0], a1 = a4[16], a2 = a4[32];

    PDL_WAIT();
    const int2* __restrict__ sb = g_state[cur];
    int cands[4];
    gather_cands(sb, p, 64, h, cands);        // trailing prop step, k = 64
    int2 st = sb[p];
    int myc = st.x;
    float sc = __int_as_float(st.y);

    prop_core(a0, a1, a2, l, h, cands, myc, sc);

    // 7 random-search steps, pixel-local (coords arithmetic, no gathers)
#pragma unroll
    for (int t = 0; t < 7; t++) {
        const int k = 1 << t;
        const int m = prop_iter & (k - 1);       // prop_iter % k
        int x0 = myc & 127, y0 = myc >> 7;

        auto coord_at = [&](int j) {
            int cx = (x0 + k * (j % 3 - 1) + m * c_DX[j] + 128) & 127;
            int cy = (y0 + k * (j / 3 - 1) + m * c_DY[j] + 128) & 127;
            return (cy << 7) | cx;
        };

        float best = -3.4e38f; int bestc = 0;
        score_pair(a0, a1, a2, l, h, coord_at(0 + h), best, bestc);
        score_pair(a0, a1, a2, l, h, coord_at(2 + h), best, bestc);
        if (sc > best) { best = sc; bestc = myc; }
        score_pair(a0, a1, a2, l, h, coord_at(5 + h), best, bestc);
        score_pair(a0, a1, a2, l, h, coord_at(7 + h), best, bestc);
        myc = bestc; sc = best;
    }

    if (FINAL) {
        if (lane == 0) {
            if (p < out_size)        out[p] = (float)myc;
            if (NPIX + p < out_size) out[NPIX + p] = sc;
        }
    } else {
        if (lane == 0) g_state[cur ^ 1][p] = make_int2(myc, __float_as_int(sc));
    }
}

// ---------------------------------------------------------------------------
template <typename K, typename... Args>
static void pdl_launch(K kern, dim3 g, dim3 b, Args... args) {
    cudaLaunchConfig_t cfg = {};
    cfg.gridDim = g;
    cfg.blockDim = b;
    cfg.stream = 0;   // legacy default stream (same as <<<>>>)
    cudaLaunchAttribute attr[1];
    attr[0].id = cudaLaunchAttributeProgrammaticStreamSerialization;
    attr[0].val.programmaticStreamSerializationAllowed = 1;
    cfg.attrs = attr;
    cfg.numAttrs = 1;
    cudaLaunchKernelEx(&cfg, kern, args...);
}

extern "C" void kernel_launch(void* const* d_in, const int* in_sizes, int n_in,
                              void* d_out, int out_size) {
    const float* input_map = (const float*)d_in[0];
    const float* ref_map   = (const float*)d_in[1];
    const float* inref_x   = (const float*)d_in[2];
    const float* inref_y   = (const float*)d_in[3];

    dim3 tg(NPIX / 128, C / 32, 2);
    transpose_kernel<<<tg, 256>>>(input_map, ref_map);

    const dim3 grid8(NPIX / 8);     // 8 warps per 256-thread block (rand7)
    const dim3 gridSW(NWARP / 4);   // single-wave: 1024 blocks x 4 warps (prop)
    const dim3 blk256(256);
    const dim3 blk128(128);

    // Iteration 0: prop k=1 (init fused), k=2..32, then rand7A (prop64 + rand).
    pdl_launch(prop_first_kernel, gridSW, blk128, inref_x, inref_y);
    int cur = 0;
    for (int k = 2; k <= 32; k *= 2) {
        pdl_launch(prop_kernel, gridSW, blk128, k, cur, cur ^ 1);
        cur ^= 1;
    }
    pdl_launch(rand7_kernel<0>, grid8, blk256, 0, cur, (float*)nullptr, 0);
    cur ^= 1;

    // Iteration 1: prop k=1..32, then rand7B (prop64 + rand + output).
    for (int k = 1; k <= 32; k *= 2) {
        pdl_launch(prop_kernel, gridSW, blk128, k, cur, cur ^ 1);
        cur ^= 1;
    }
    pdl_launch(rand7_kernel<1>, grid8, blk256, 1, cur, (float*)d_out, out_size);
}

// round 16
// speedup vs baseline: 1.1465x; 1.1465x over previous
#include <cuda_runtime.h>
#include <cuda_bf16.h>

// PatchMatch (b=1, c=192, h=w=128); fixed: iteration_count=2, minWH=127, is_final=1.
// Launch plan (15 kernels, PDL overlap on all eval->eval edges):
//   transpose | prop_first(k=1,init) prop(2..32)x5 rand7A(prop64+7 rand)
//             | prop(1..32)x6 rand7B(prop64+7 rand+output)
// R14 structure (best measured: warp-per-pixel, 128-thr prop blocks);
// rand7 kernels now also 128-thr blocks (finer RF/tail granularity).

#define C 192
#define NF4 48          // 192 floats = 48 float4
#define H 128
#define W 128
#define NPIX (H * W)

#define PDL_SIGNAL() asm volatile("griddepcontrol.launch_dependents;")
#define PDL_WAIT()   asm volatile("griddepcontrol.wait;" ::: "memory")

__device__ float4 g_in_t4[NPIX * NF4];    // pixel-major input  [p][48]
__device__ float4 g_ref_t4[NPIX * NF4];   // pixel-major ref    [p][48]
__device__ int2   g_state[2][NPIX];       // {packed y*128+x, float bits of score}

__constant__ int c_DX[9] = {0, -1, -1, 0, 0, 0, 1, 1, 0};
__constant__ int c_DY[9] = {1, 0, 0, 1, 0, -1, 0, 0, -1};

// ---------------------------------------------------------------------------
// Vectorized transpose [C][NPIX] -> [NPIX][C]. Tile: 32 channels x 128 pixels.
__global__ __launch_bounds__(256) void transpose_kernel(
    const float* __restrict__ in0, const float* __restrict__ in1) {
    __shared__ float tile[32][129];
    const float* in = blockIdx.z ? in1 : in0;
    float* out = blockIdx.z ? (float*)g_ref_t4 : (float*)g_in_t4;
    int p0 = blockIdx.x * 128;
    int c0 = blockIdx.y * 32;
    int tid = threadIdx.x;

#pragma unroll
    for (int pass = 0; pass < 4; pass++) {
        int r = pass * 8 + (tid >> 5);
        int p4 = tid & 31;
        const float4* inv = (const float4*)(in + (size_t)(c0 + r) * NPIX + p0);
        float4 v = inv[p4];
        tile[r][4 * p4 + 0] = v.x;
        tile[r][4 * p4 + 1] = v.y;
        tile[r][4 * p4 + 2] = v.z;
        tile[r][4 * p4 + 3] = v.w;
    }
    __syncthreads();

#pragma unroll
    for (int pass = 0; pass < 4; pass++) {
        int pix = pass * 32 + (tid >> 3);
        int c4 = tid & 7;
        float4 w;
        w.x = tile[4 * c4 + 0][pix];
        w.y = tile[4 * c4 + 1][pix];
        w.z = tile[4 * c4 + 2][pix];
        w.w = tile[4 * c4 + 3][pix];
        float4* outv = (float4*)(out + (size_t)(p0 + pix) * C + c0);
        outv[c4] = w;
    }
}

// ---------------------------------------------------------------------------
// Canonical per-lane (l in [0,16)) partial dot; identical everywhere so equal
// coords give bit-identical scores. r4 is pre-offset by l.
__device__ __forceinline__ float dot48h(float4 a0, float4 a1, float4 a2,
                                        const float4* __restrict__ r4) {
    float4 r0 = r4[0], r1 = r4[16], r2 = r4[32];
    float s;
    s = a0.x * r0.x;          s = fmaf(a0.y, r0.y, s);
    s = fmaf(a0.z, r0.z, s);  s = fmaf(a0.w, r0.w, s);
    s = fmaf(a1.x, r1.x, s);  s = fmaf(a1.y, r1.y, s);
    s = fmaf(a1.z, r1.z, s);  s = fmaf(a1.w, r1.w, s);
    s = fmaf(a2.x, r2.x, s);  s = fmaf(a2.y, r2.y, s);
    s = fmaf(a2.z, r2.z, s);  s = fmaf(a2.w, r2.w, s);
    return s;
}

__device__ __forceinline__ float halfsum(float s) {
    s += __shfl_xor_sync(0xffffffffu, s, 8);
    s += __shfl_xor_sync(0xffffffffu, s, 4);
    s += __shfl_xor_sync(0xffffffffu, s, 2);
    s += __shfl_xor_sync(0xffffffffu, s, 1);
    return s;
}

__device__ __forceinline__ int reflect128(int t) {
    if (t < 0) t = -t;
    if (t > 127) t = 254 - t;
    return t;
}

// Score a pair of candidates (this half's cc; other half's via shuffle) and
// fold in index order jA then jA+1 (strict > == first-occurrence argmax).
__device__ __forceinline__ void score_pair(float4 a0, float4 a1, float4 a2, int l,
                                           int h, int cc, float& best, int& bestc) {
    float s = halfsum(dot48h(a0, a1, a2, g_ref_t4 + (size_t)cc * NF4 + l));
    float sO = __shfl_xor_sync(0xffffffffu, s, 16);
    int   cO = __shfl_xor_sync(0xffffffffu, cc, 16);
    float s0 = h ? sO : s;  int c0 = h ? cO : cc;
    float s1 = h ? s : sO;  int c1 = h ? cc : cO;
    if (s0 > best) { best = s0; bestc = c0; }
    if (s1 > best) { best = s1; bestc = c1; }
}

// One step with PRE-FETCHED candidate coords cands[4] (j = {0,2,5,7}+h).
__device__ __forceinline__ void prop_core(float4 a0, float4 a1, float4 a2,
                                          int l, int h, const int* cands,
                                          int& myc, float& sc) {
    float best = -3.4e38f; int bestc = 0;
    score_pair(a0, a1, a2, l, h, cands[0], best, bestc);
    score_pair(a0, a1, a2, l, h, cands[1], best, bestc);
    if (sc > best) { best = sc; bestc = myc; }
    score_pair(a0, a1, a2, l, h, cands[2], best, bestc);
    score_pair(a0, a1, a2, l, h, cands[3], best, bestc);
    myc = bestc; sc = best;
}

// Gather the 4 per-half candidate coords for a prop step (independent loads).
__device__ __forceinline__ void gather_cands(const int2* __restrict__ sb,
                                             int p, int k, int h, int* cands) {
    const int jb[4] = {0, 2, 5, 7};
    int y = p >> 7, x = p & 127;
#pragma unroll
    for (int i = 0; i < 4; i++) {
        int j = jb[i] + h;
        int ny = reflect128(y + k * (j / 3 - 1));
        int nx = reflect128(x + k * (j % 3 - 1));
        cands[i] = ((const int*)sb)[2 * ((ny << 7) + nx)];   // coord word only
    }
}

// ---------------------------------------------------------------------------
// Step 0 (prop, k=1) with init fused: neighbor coords straight from inref_x/y;
// center score computed as a 9th dot. 128-thr blocks like prop.
__global__ __launch_bounds__(128, 10) void prop_first_kernel(
    const float* __restrict__ inref_x, const float* __restrict__ inref_y) {
    PDL_SIGNAL();
    PDL_WAIT();
    int warp = blockIdx.x * 4 + (threadIdx.x >> 5);
    int lane = threadIdx.x & 31;
    int h = lane >> 4, l = lane & 15;
    int p = warp;
    int y = p >> 7, x = p & 127;

    const float4* __restrict__ a4 = g_in_t4 + (size_t)p * NF4 + l;
    float4 a0 = a4[0], a1 = a4[16], a2 = a4[32];

    const int jb[4] = {0, 2, 5, 7};
    int cands[4];
#pragma unroll
    for (int i = 0; i < 4; i++) {
        int j = jb[i] + h;
        int ny = reflect128(y + (j / 3 - 1));
        int nx = reflect128(x + (j % 3 - 1));
        int np = (ny << 7) + nx;
        cands[i] = ((int)inref_y[np] << 7) + (int)inref_x[np];
    }
    int cc4 = ((int)inref_y[p] << 7) + (int)inref_x[p];

    float best = -3.4e38f; int bestc = 0;
    score_pair(a0, a1, a2, l, h, cands[0], best, bestc);
    score_pair(a0, a1, a2, l, h, cands[1], best, bestc);
    {   // center candidate j=4
        float s4 = halfsum(dot48h(a0, a1, a2, g_ref_t4 + (size_t)cc4 * NF4 + l));
        if (s4 > best) { best = s4; bestc = cc4; }
    }
    score_pair(a0, a1, a2, l, h, cands[2], best, bestc);
    score_pair(a0, a1, a2, l, h, cands[3], best, bestc);

    if (lane == 0) g_state[0][p] = make_int2(bestc, __float_as_int(best));
}

// ---------------------------------------------------------------------------
// Propagation step (k >= 2). Warp per pixel, 128-thr blocks, 51-reg cap.
// Input loads overlap predecessor tail via PDL; gathers issue first post-wait.
__global__ __launch_bounds__(128, 10) void prop_kernel(int k, int cur, int nxt) {
    PDL_SIGNAL();
    int warp = blockIdx.x * 4 + (threadIdx.x >> 5);
    int lane = threadIdx.x & 31;
    int h = lane >> 4, l = lane & 15;
    int p = warp;

    const float4* __restrict__ a4 = g_in_t4 + (size_t)p * NF4 + l;
    float4 a0 = a4[0], a1 = a4[16], a2 = a4[32];

    PDL_WAIT();
    const int2* __restrict__ sb = g_state[cur];
    int cands[4];
    gather_cands(sb, p, k, h, cands);
    int2 st = sb[p];
    int myc = st.x;
    float sc = __int_as_float(st.y);

    prop_core(a0, a1, a2, l, h, cands, myc, sc);

    if (lane == 0) g_state[nxt][p] = make_int2(myc, __float_as_int(sc));
}

// ---------------------------------------------------------------------------
// Fused: one prop step (k=64) + 7 random-search steps (k=1..64), state in
// registers. No reg cap (caps spill this kernel); 128-thr blocks for finer
// RF/tail granularity. Writes the OTHER state buffer. FINAL=1 writes output.
template <int FINAL>
__global__ __launch_bounds__(128) void rand7_kernel(int prop_iter, int cur,
                                                    float* __restrict__ out,
                                                    int out_size) {
    PDL_SIGNAL();
    int warp = blockIdx.x * 4 + (threadIdx.x >> 5);
    int lane = threadIdx.x & 31;
    int h = lane >> 4, l = lane & 15;
    int p = warp;

    const float4* __restrict__ a4 = g_in_t4 + (size_t)p * NF4 + l;
    float4 a0 = a4[0], a1 = a4[16], a2 = a4[32];

    PDL_WAIT();
    const int2* __restrict__ sb = g_state[cur];
    int cands[4];
    gather_cands(sb, p, 64, h, cands);        // trailing prop step, k = 64
    int2 st = sb[p];
    int myc = st.x;
    float sc = __int_as_float(st.y);

    prop_core(a0, a1, a2, l, h, cands, myc, sc);

    // 7 random-search steps, pixel-local (coords arithmetic, no gathers)
#pragma unroll
    for (int t = 0; t < 7; t++) {
        const int k = 1 << t;
        const int m = prop_iter & (k - 1);       // prop_iter % k
        int x0 = myc & 127, y0 = myc >> 7;

        auto coord_at = [&](int j) {
            int cx = (x0 + k * (j % 3 - 1) + m * c_DX[j] + 128) & 127;
            int cy = (y0 + k * (j / 3 - 1) + m * c_DY[j] + 128) & 127;
            return (cy << 7) | cx;
        };

        float best = -3.4e38f; int bestc = 0;
        score_pair(a0, a1, a2, l, h, coord_at(0 + h), best, bestc);
        score_pair(a0, a1, a2, l, h, coord_at(2 + h), best, bestc);
        if (sc > best) { best = sc; bestc = myc; }
        score_pair(a0, a1, a2, l, h, coord_at(5 + h), best, bestc);
        score_pair(a0, a1, a2, l, h, coord_at(7 + h), best, bestc);
        myc = bestc; sc = best;
    }

    if (FINAL) {
        if (lane == 0) {
            if (p < out_size)        out[p] = (float)myc;
            if (NPIX + p < out_size) out[NPIX + p] = sc;
        }
    } else {
        if (lane == 0) g_state[cur ^ 1][p] = make_int2(myc, __float_as_int(sc));
    }
}

// ---------------------------------------------------------------------------
template <typename K, typename... Args>
static void pdl_launch(K kern, dim3 g, dim3 b, Args... args) {
    cudaLaunchConfig_t cfg = {};
    cfg.gridDim = g;
    cfg.blockDim = b;
    cfg.stream = 0;   // legacy default stream (same as <<<>>>)
    cudaLaunchAttribute attr[1];
    attr[0].id = cudaLaunchAttributeProgrammaticStreamSerialization;
    attr[0].val.programmaticStreamSerializationAllowed = 1;
    cfg.attrs = attr;
    cfg.numAttrs = 1;
    cudaLaunchKernelEx(&cfg, kern, args...);
}

extern "C" void kernel_launch(void* const* d_in, const int* in_sizes, int n_in,
                              void* d_out, int out_size) {
    const float* input_map = (const float*)d_in[0];
    const float* ref_map   = (const float*)d_in[1];
    const float* inref_x   = (const float*)d_in[2];
    const float* inref_y   = (const float*)d_in[3];

    dim3 tg(NPIX / 128, C / 32, 2);
    transpose_kernel<<<tg, 256>>>(input_map, ref_map);

    const dim3 grid4(NPIX / 4);   // warp per pixel, 4 warps per 128-thr block
    const dim3 blk128(128);

    // Iteration 0: prop k=1 (init fused), k=2..32, then rand7A (prop64 + rand).
    pdl_launch(prop_first_kernel, grid4, blk128, inref_x, inref_y);
    int cur = 0;
    for (int k = 2; k <= 32; k *= 2) {
        pdl_launch(prop_kernel, grid4, blk128, k, cur, cur ^ 1);
        cur ^= 1;
    }
    pdl_launch(rand7_kernel<0>, grid4, blk128, 0, cur, (float*)nullptr, 0);
    cur ^= 1;

    // Iteration 1: prop k=1..32, then rand7B (prop64 + rand + output).
    for (int k = 1; k <= 32; k *= 2) {
        pdl_launch(prop_kernel, grid4, blk128, k, cur, cur ^ 1);
        cur ^= 1;
    }
    pdl_launch(rand7_kernel<1>, grid4, blk128, 1, cur, (float*)d_out, out_size);
}